// round 2
// baseline (speedup 1.0000x reference)
#include <cuda_runtime.h>

#define B_  2
#define H_  8
#define LQ  256
#define LK  512
#define DM  512
#define DK  64

// Scratch (device globals — no allocations allowed)
__device__ float g_Q[B_*LQ*DM];   // rows b*LQ+i, col h*64+d
__device__ float g_K[B_*LK*DM];
__device__ float g_V[B_*LK*DM];
__device__ float g_X[B_*LQ*DM];
__device__ int   g_idx[B_*LK];    // compacted unmasked j per batch
__device__ int   g_cnt[B_];
__device__ float g_mult[B_];      // 0 if all masked (uniform fallback), else 1

__device__ __forceinline__ float fast_tanh(float x) {
    float r; asm("tanh.approx.f32 %0, %1;" : "=f"(r) : "f"(x)); return r;
}

// ---------------------------------------------------------------------------
// Deterministic mask compaction: one block per batch, Hillis–Steele scan.
// ---------------------------------------------------------------------------
__global__ void compact_kernel(const int* __restrict__ mask) {
    __shared__ int s[LK];
    int b = blockIdx.x, t = threadIdx.x;
    int m = (mask[b*LK + t] != 0) ? 1 : 0;
    s[t] = m;
    __syncthreads();
    for (int off = 1; off < LK; off <<= 1) {
        int v = 0;
        if (t >= off) v = s[t - off];
        __syncthreads();
        if (t >= off) s[t] += v;
        __syncthreads();
    }
    int total = s[LK-1];
    if (m) g_idx[b*LK + s[t] - 1] = t;
    if (total == 0) g_idx[b*LK + t] = t;   // all-masked: softmax(-1e9 all) = uniform
    if (t == 0) {
        g_cnt[b]  = (total == 0) ? LK : total;
        g_mult[b] = (total == 0) ? 0.f : 1.f;
    }
}

// ---------------------------------------------------------------------------
// Shared fp32 GEMM body: C[m0+.., n0+..] = A @ W, K=N=512.
// 64x64 tile, BK=16, 4x4 micro-tile, register prefetch of next gmem tiles.
// ---------------------------------------------------------------------------
__device__ __forceinline__ void gemm_body(const float* __restrict__ A,
                                          const float* __restrict__ Bw,
                                          float* __restrict__ C,
                                          int m0, int n0)
{
    __shared__ __align__(16) float As[16][68];   // [k][m], padded
    __shared__ __align__(16) float Bs[16][68];   // [k][n], padded

    int t = threadIdx.x;
    int arow = t >> 2,  akc = (t & 3) * 4;     // A tile: 64 rows x 4 float4
    int bkr  = t >> 4,  bnc = (t & 15) * 4;    // B tile: 16 rows x 16 float4

    const float* Ap = A  + (m0 + arow) * DM + akc;
    const float* Bp = Bw + bkr * DM + n0 + bnc;

    float4 pa = *(const float4*)Ap;
    float4 pb = *(const float4*)Bp;

    int tx = t & 15, ty = t >> 4;
    float acc[4][4];
    #pragma unroll
    for (int i = 0; i < 4; i++)
        #pragma unroll
        for (int j = 0; j < 4; j++) acc[i][j] = 0.f;

    for (int k0 = 0; k0 < DM; k0 += 16) {
        As[akc+0][arow] = pa.x; As[akc+1][arow] = pa.y;
        As[akc+2][arow] = pa.z; As[akc+3][arow] = pa.w;
        *(float4*)&Bs[bkr][bnc] = pb;
        __syncthreads();
        if (k0 + 16 < DM) {
            pa = *(const float4*)(Ap + k0 + 16);
            pb = *(const float4*)(Bp + (k0 + 16) * DM);
        }
        #pragma unroll
        for (int kk = 0; kk < 16; kk++) {
            float4 a4 = *(const float4*)&As[kk][ty*4];
            float4 b4 = *(const float4*)&Bs[kk][tx*4];
            float av[4] = {a4.x, a4.y, a4.z, a4.w};
            float bv[4] = {b4.x, b4.y, b4.z, b4.w};
            #pragma unroll
            for (int i = 0; i < 4; i++)
                #pragma unroll
                for (int j = 0; j < 4; j++)
                    acc[i][j] += av[i] * bv[j];
        }
        __syncthreads();
    }
    #pragma unroll
    for (int i = 0; i < 4; i++) {
        float4 o = make_float4(acc[i][0], acc[i][1], acc[i][2], acc[i][3]);
        *(float4*)&C[(m0 + ty*4 + i) * DM + n0 + tx*4] = o;
    }
}

// ---------------------------------------------------------------------------
// Fused Q/K/V projections in ONE launch: blockIdx.z selects which GEMM.
// z=0: Q = query @ Wq (512 rows) ; z=1: K ; z=2: V (1024 rows each).
// Grid (8, 16, 3); the 8 extra y-blocks of z=0 exit immediately.
// ---------------------------------------------------------------------------
__global__ void __launch_bounds__(256) proj_kernel(const float* __restrict__ query,
                                                   const float* __restrict__ key_,
                                                   const float* __restrict__ value,
                                                   const float* __restrict__ Wq,
                                                   const float* __restrict__ Wk,
                                                   const float* __restrict__ Wv)
{
    int z = blockIdx.z;
    const float* A; const float* W; float* C; int mrows;
    if (z == 0)      { A = query; W = Wq; C = g_Q; mrows = B_*LQ; }
    else if (z == 1) { A = key_;  W = Wk; C = g_K; mrows = B_*LK; }
    else             { A = value; W = Wv; C = g_V; mrows = B_*LK; }
    int m0 = blockIdx.y * 64;
    if (m0 >= mrows) return;
    gemm_body(A, W, C, m0, blockIdx.x * 64);
}

// out = X @ Wo
__global__ void __launch_bounds__(256) out_gemm(const float* __restrict__ Wo,
                                                float* __restrict__ out)
{
    gemm_body(g_X, Wo, out, blockIdx.y * 64, blockIdx.x * 64);
}

// ---------------------------------------------------------------------------
// Fused additive attention: per block = (b, h, 32 q-rows).
// Loop over compacted (unmasked) k/v in chunks of 32, register-prefetched.
// Phase 1: e_ij = exp( sum_d tanh(q+k)*wa ) into shared (MUFU-bound).
// Phase 2: acc_i[d] += e_ij * v_j[d]; denom_i += e_ij  (FMA-bound).
// No max-subtraction needed: |score| <= ||wa||_1 ~ 1.
// ---------------------------------------------------------------------------
__global__ void __launch_bounds__(256, 2) attn_kernel(const float* __restrict__ wa)
{
    __shared__ __align__(16) float qs[32][68];
    __shared__ __align__(16) float ks[32][68];
    __shared__ __align__(16) float vs[32][68];
    __shared__ float es[32][33];
    __shared__ __align__(16) float was[64];

    int blk = blockIdx.x;
    int ib = blk & 7, h = (blk >> 3) & 7, b = blk >> 6;
    int t = threadIdx.x, lane = t & 31, w = t >> 5;

    if (t < 64) was[t] = wa[t];

    const float* Qb = g_Q + (b*LQ + ib*32) * DM + h*DK;
    #pragma unroll
    for (int u = 0; u < 2; u++) {
        int r = t + u*256;
        int row = r >> 4, c4 = (r & 15) * 4;
        *(float4*)&qs[row][c4] = *(const float4*)&Qb[row*DM + c4];
    }

    int cnt    = g_cnt[b];
    float mult = g_mult[b];
    int nchunk = (cnt + 31) >> 5;

    float4 acc0 = make_float4(0,0,0,0), acc1 = make_float4(0,0,0,0);
    float denom = 0.f;
    int i2 = t >> 3, g = t & 7;

    const float* Kbase = g_K + b*LK*DM + h*DK;
    const float* Vbase = g_V + b*LK*DM + h*DK;
    const int*   idxb  = g_idx + b*LK;

    float4 pk[2], pv[2];
    #pragma unroll
    for (int u = 0; u < 2; u++) {                 // prefetch chunk 0
        int r = t + u*256;
        int row = r >> 4, c4 = (r & 15) * 4;
        int src = (row < cnt) ? idxb[row] : 0;
        pk[u] = *(const float4*)&Kbase[src*DM + c4];
        pv[u] = *(const float4*)&Vbase[src*DM + c4];
    }

    for (int c = 0; c < nchunk; c++) {
        #pragma unroll
        for (int u = 0; u < 2; u++) {
            int r = t + u*256;
            int row = r >> 4, c4 = (r & 15) * 4;
            *(float4*)&ks[row][c4] = pk[u];
            *(float4*)&vs[row][c4] = pv[u];
        }
        __syncthreads();
        if (c + 1 < nchunk) {                     // prefetch next chunk
            #pragma unroll
            for (int u = 0; u < 2; u++) {
                int r = t + u*256;
                int row = r >> 4, c4 = (r & 15) * 4;
                int jj = (c + 1)*32 + row;
                int src = (jj < cnt) ? idxb[jj] : 0;
                pk[u] = *(const float4*)&Kbase[src*DM + c4];
                pv[u] = *(const float4*)&Vbase[src*DM + c4];
            }
        }
        // Phase 1: warp w owns rows i = 4w..4w+3, lane = local j
        bool valid = (c*32 + lane) < cnt;
        #pragma unroll
        for (int ii = 0; ii < 4; ii++) {
            int i = w*4 + ii;
            float s = 0.f;
            #pragma unroll
            for (int d4 = 0; d4 < 16; d4++) {
                float4 q4 = *(const float4*)&qs[i][d4*4];
                float4 k4 = *(const float4*)&ks[lane][d4*4];
                float4 w4 = *(const float4*)&was[d4*4];
                s += fast_tanh(q4.x + k4.x) * w4.x;
                s += fast_tanh(q4.y + k4.y) * w4.y;
                s += fast_tanh(q4.z + k4.z) * w4.z;
                s += fast_tanh(q4.w + k4.w) * w4.w;
            }
            es[i][lane] = valid ? __expf(s * mult) : 0.f;
        }
        __syncthreads();
        // Phase 2: thread owns (i2, d-groups g*4 and 32+g*4)
        #pragma unroll
        for (int j = 0; j < 32; j++) {
            float e = es[i2][j];
            float4 v0 = *(const float4*)&vs[j][g*4];
            float4 v1 = *(const float4*)&vs[j][32 + g*4];
            acc0.x += e*v0.x; acc0.y += e*v0.y; acc0.z += e*v0.z; acc0.w += e*v0.w;
            acc1.x += e*v1.x; acc1.y += e*v1.y; acc1.z += e*v1.z; acc1.w += e*v1.w;
            denom += e;
        }
        __syncthreads();
    }

    float inv = 1.f / denom;
    float* Xb = g_X + (b*LQ + ib*32 + i2) * DM + h*DK;
    *(float4*)&Xb[g*4]      = make_float4(acc0.x*inv, acc0.y*inv, acc0.z*inv, acc0.w*inv);
    *(float4*)&Xb[32 + g*4] = make_float4(acc1.x*inv, acc1.y*inv, acc1.z*inv, acc1.w*inv);
}

// ---------------------------------------------------------------------------
extern "C" void kernel_launch(void* const* d_in, const int* in_sizes, int n_in,
                              void* d_out, int out_size)
{
    const float* query = (const float*)d_in[0];
    const float* key_  = (const float*)d_in[1];
    const float* value = (const float*)d_in[2];
    const int*   mask  = (const int*)  d_in[3];
    const float* Wq    = (const float*)d_in[4];
    const float* Wk    = (const float*)d_in[5];
    const float* Wv    = (const float*)d_in[6];
    const float* Wo    = (const float*)d_in[7];
    const float* wa    = (const float*)d_in[8];
    float* out = (float*)d_out;

    proj_kernel<<<dim3(8, 16, 3), 256>>>(query, key_, value, Wq, Wk, Wv);
    compact_kernel<<<2, 512>>>(mask);
    attn_kernel<<<128, 256>>>(wa);
    out_gemm<<<dim3(8, 8), 256>>>(Wo, out);
}

// round 9
// speedup vs baseline: 1.1495x; 1.1495x over previous
#include <cuda_runtime.h>

#define B_  2
#define H_  8
#define LQ  256
#define LK  512
#define DM  512
#define DK  64

// Scratch (device globals — no allocations allowed)
__device__ float g_Q[B_*LQ*DM];
__device__ float g_K[B_*LK*DM];
__device__ float g_V[B_*LK*DM];
__device__ float g_X[B_*LQ*DM];
__device__ float g_P[3][DM*DM];   // split-K partials for out GEMM (z=1..3)
__device__ int   g_idx[B_*LK];
__device__ int   g_cnt[B_];
__device__ float g_mult[B_];

__device__ __forceinline__ float fast_tanh(float x) {
    float r; asm("tanh.approx.f32 %0, %1;" : "=f"(r) : "f"(x)); return r;
}

// ---------------------------------------------------------------------------
// Deterministic mask compaction, 256 threads per batch: pair-load + scan.
// Runs inside otherwise-idle proj_kernel blocks.
// ---------------------------------------------------------------------------
__device__ void compact_body(const int* __restrict__ mask, int b) {
    __shared__ int s[256];
    int t = threadIdx.x;
    int m0 = (mask[b*LK + 2*t]     != 0) ? 1 : 0;
    int m1 = (mask[b*LK + 2*t + 1] != 0) ? 1 : 0;
    int ps = m0 + m1;
    s[t] = ps;
    __syncthreads();
    for (int off = 1; off < 256; off <<= 1) {
        int v = (t >= off) ? s[t - off] : 0;
        __syncthreads();
        if (t >= off) s[t] += v;
        __syncthreads();
    }
    int incl  = s[t];
    int total = s[255];
    int r0 = incl - ps + m0;     // inclusive rank of element 2t
    int r1 = incl;               // inclusive rank of element 2t+1
    if (m0) g_idx[b*LK + r0 - 1] = 2*t;
    if (m1) g_idx[b*LK + r1 - 1] = 2*t + 1;
    if (total == 0) {            // all-masked: uniform softmax fallback
        g_idx[b*LK + 2*t]     = 2*t;
        g_idx[b*LK + 2*t + 1] = 2*t + 1;
    }
    if (t == 0) {
        g_cnt[b]  = (total == 0) ? LK : total;
        g_mult[b] = (total == 0) ? 0.f : 1.f;
    }
}

// ---------------------------------------------------------------------------
// fp32 GEMM body: C[m0.., n0..] = A[:, kbeg..] @ W[kbeg.., n0..] over nk*16 K.
// 64x64 tile, BK=16, 4x4 micro-tile. DOUBLE-BUFFERED smem: one sync per iter.
// ---------------------------------------------------------------------------
__device__ __forceinline__ void gemm_body(const float* __restrict__ A,
                                          const float* __restrict__ Bw,
                                          float* __restrict__ C,
                                          int m0, int n0, int kbeg, int nk)
{
    __shared__ __align__(16) float As[2][16][68];   // [buf][k][m]
    __shared__ __align__(16) float Bs[2][16][68];   // [buf][k][n]

    int t = threadIdx.x;
    int arow = t >> 2,  akc = (t & 3) * 4;     // A tile: 64 rows x 4 float4
    int bkr  = t >> 4,  bnc = (t & 15) * 4;    // B tile: 16 rows x 16 float4

    const float* Ap = A  + (m0 + arow) * DM + kbeg + akc;
    const float* Bp = Bw + (kbeg + bkr) * DM + n0 + bnc;

    float4 pa = *(const float4*)Ap;
    float4 pb = *(const float4*)Bp;

    int tx = t & 15, ty = t >> 4;
    float acc[4][4];
    #pragma unroll
    for (int i = 0; i < 4; i++)
        #pragma unroll
        for (int j = 0; j < 4; j++) acc[i][j] = 0.f;

    As[0][akc+0][arow] = pa.x; As[0][akc+1][arow] = pa.y;
    As[0][akc+2][arow] = pa.z; As[0][akc+3][arow] = pa.w;
    *(float4*)&Bs[0][bkr][bnc] = pb;
    __syncthreads();

    int cur = 0;
    for (int kt = 0; kt < nk; kt++) {
        bool more = (kt + 1 < nk);
        if (more) {                               // issue gmem loads early
            pa = *(const float4*)(Ap + (kt + 1) * 16);
            pb = *(const float4*)(Bp + (kt + 1) * 16 * DM);
        }
        #pragma unroll
        for (int kk = 0; kk < 16; kk++) {
            float4 a4 = *(const float4*)&As[cur][kk][ty*4];
            float4 b4 = *(const float4*)&Bs[cur][kk][tx*4];
            float av[4] = {a4.x, a4.y, a4.z, a4.w};
            float bv[4] = {b4.x, b4.y, b4.z, b4.w};
            #pragma unroll
            for (int i = 0; i < 4; i++)
                #pragma unroll
                for (int j = 0; j < 4; j++)
                    acc[i][j] += av[i] * bv[j];
        }
        if (more) {                               // fill the other buffer
            int nxt = cur ^ 1;
            As[nxt][akc+0][arow] = pa.x; As[nxt][akc+1][arow] = pa.y;
            As[nxt][akc+2][arow] = pa.z; As[nxt][akc+3][arow] = pa.w;
            *(float4*)&Bs[nxt][bkr][bnc] = pb;
        }
        __syncthreads();
        cur ^= 1;
    }
    #pragma unroll
    for (int i = 0; i < 4; i++) {
        float4 o = make_float4(acc[i][0], acc[i][1], acc[i][2], acc[i][3]);
        *(float4*)&C[(m0 + ty*4 + i) * DM + n0 + tx*4] = o;
    }
}

// ---------------------------------------------------------------------------
// Fused Q/K/V projections + mask compaction. Grid (8,16,3).
// z=0,y<8: Q GEMM. z=1/2: K/V GEMMs. z=0,y==8,x<2: compaction (idle blocks).
// ---------------------------------------------------------------------------
__global__ void __launch_bounds__(256) proj_kernel(const float* __restrict__ query,
                                                   const float* __restrict__ key_,
                                                   const float* __restrict__ value,
                                                   const float* __restrict__ Wq,
                                                   const float* __restrict__ Wk,
                                                   const float* __restrict__ Wv,
                                                   const int* __restrict__ mask)
{
    int z = blockIdx.z;
    const float* A; const float* W; float* C; int mrows;
    if (z == 0)      { A = query; W = Wq; C = g_Q; mrows = B_*LQ; }
    else if (z == 1) { A = key_;  W = Wk; C = g_K; mrows = B_*LK; }
    else             { A = value; W = Wv; C = g_V; mrows = B_*LK; }
    int m0 = blockIdx.y * 64;
    if (m0 >= mrows) {
        if (z == 0 && blockIdx.y == 8 && blockIdx.x < 2)
            compact_body(mask, blockIdx.x);
        return;
    }
    gemm_body(A, W, C, m0, blockIdx.x * 64, 0, DM/16);
}

// ---------------------------------------------------------------------------
// out = X @ Wo, SPLIT-K=4: z=0 writes d_out, z=1..3 write g_P[z-1].
// Grid (8,8,4) = 256 CTAs (was 64 → latency-bound at occ 12.5%).
// ---------------------------------------------------------------------------
__global__ void __launch_bounds__(256) out_gemm(const float* __restrict__ Wo,
                                                float* __restrict__ out)
{
    int z = blockIdx.z;
    float* C = (z == 0) ? out : g_P[z-1];
    gemm_body(g_X, Wo, C, blockIdx.y * 64, blockIdx.x * 64, z * (DM/4), DM/64);
}

// Deterministic fixed-order reduction of the 3 partial buffers into out.
__global__ void __launch_bounds__(256) reduce_out(float* __restrict__ out)
{
    int i = (blockIdx.x * 256 + threadIdx.x) * 2;   // float4 index, 2 per thread
    float4* o4 = (float4*)out;
    #pragma unroll
    for (int u = 0; u < 2; u++) {
        int k = i + u;
        float4 a = o4[k];
        float4 p0 = ((const float4*)g_P[0])[k];
        float4 p1 = ((const float4*)g_P[1])[k];
        float4 p2 = ((const float4*)g_P[2])[k];
        a.x += p0.x + p1.x + p2.x;
        a.y += p0.y + p1.y + p2.y;
        a.z += p0.z + p1.z + p2.z;
        a.w += p0.w + p1.w + p2.w;
        o4[k] = a;
    }
}

// ---------------------------------------------------------------------------
// Fused additive attention. Block = (b, h, 16 q-rows) -> grid 256.
// Phase 1 (MUFU-bound): e_ij = exp( sum_d tanh(q+k)*wa ), 4 independent
// accumulation chains. Phase 2 (FMA): acc += e*v, denom += e.
// |score| <= ||wa||_1 ~ 1 so no max-subtraction needed.
// ---------------------------------------------------------------------------
__global__ void __launch_bounds__(256, 2) attn_kernel(const float* __restrict__ wa)
{
    __shared__ __align__(16) float qs[16][68];
    __shared__ __align__(16) float ks[32][68];
    __shared__ __align__(16) float vs[32][68];
    __shared__ float es[16][33];
    __shared__ __align__(16) float was[64];

    int blk = blockIdx.x;
    int ib = blk & 15, h = (blk >> 4) & 7, b = blk >> 7;
    int t = threadIdx.x, lane = t & 31, w = t >> 5;

    if (t < 64) was[t] = wa[t];

    const float* Qb = g_Q + (b*LQ + ib*16) * DM + h*DK;
    {   // 16 rows x 16 float4 = 256 loads, one per thread
        int row = t >> 4, c4 = (t & 15) * 4;
        *(float4*)&qs[row][c4] = *(const float4*)&Qb[row*DM + c4];
    }

    int cnt    = g_cnt[b];
    float mult = g_mult[b];
    int nchunk = (cnt + 31) >> 5;

    float4 acc = make_float4(0,0,0,0);
    float denom = 0.f;
    int i2 = t >> 4, g = t & 15;

    const float* Kbase = g_K + b*LK*DM + h*DK;
    const float* Vbase = g_V + b*LK*DM + h*DK;
    const int*   idxb  = g_idx + b*LK;

    float4 pk[2], pv[2];
    #pragma unroll
    for (int u = 0; u < 2; u++) {                 // prefetch chunk 0
        int r = t + u*256;
        int row = r >> 4, c4 = (r & 15) * 4;
        int src = (row < cnt) ? idxb[row] : 0;
        pk[u] = *(const float4*)&Kbase[src*DM + c4];
        pv[u] = *(const float4*)&Vbase[src*DM + c4];
    }

    for (int c = 0; c < nchunk; c++) {
        #pragma unroll
        for (int u = 0; u < 2; u++) {
            int r = t + u*256;
            int row = r >> 4, c4 = (r & 15) * 4;
            *(float4*)&ks[row][c4] = pk[u];
            *(float4*)&vs[row][c4] = pv[u];
        }
        __syncthreads();
        if (c + 1 < nchunk) {                     // prefetch next chunk
            #pragma unroll
            for (int u = 0; u < 2; u++) {
                int r = t + u*256;
                int row = r >> 4, c4 = (r & 15) * 4;
                int jj = (c + 1)*32 + row;
                int src = (jj < cnt) ? idxb[jj] : 0;
                pk[u] = *(const float4*)&Kbase[src*DM + c4];
                pv[u] = *(const float4*)&Vbase[src*DM + c4];
            }
        }
        // Phase 1: warp w owns rows 2w, 2w+1; lane = local j.
        bool valid = (c*32 + lane) < cnt;
        #pragma unroll
        for (int ii = 0; ii < 2; ii++) {
            int i = w*2 + ii;
            float s0 = 0.f, s1 = 0.f, s2 = 0.f, s3 = 0.f;  // 4 indep chains
            #pragma unroll
            for (int d4 = 0; d4 < 16; d4++) {
                float4 q4 = *(const float4*)&qs[i][d4*4];
                float4 k4 = *(const float4*)&ks[lane][d4*4];
                float4 w4 = *(const float4*)&was[d4*4];
                s0 += fast_tanh(q4.x + k4.x) * w4.x;
                s1 += fast_tanh(q4.y + k4.y) * w4.y;
                s2 += fast_tanh(q4.z + k4.z) * w4.z;
                s3 += fast_tanh(q4.w + k4.w) * w4.w;
            }
            float s = (s0 + s1) + (s2 + s3);
            es[i][lane] = valid ? __expf(s * mult) : 0.f;
        }
        __syncthreads();
        // Phase 2: thread owns (row i2, d-group g*4).
        #pragma unroll
        for (int j = 0; j < 32; j++) {
            float e = es[i2][j];
            float4 v = *(const float4*)&vs[j][g*4];
            acc.x += e*v.x; acc.y += e*v.y; acc.z += e*v.z; acc.w += e*v.w;
            denom += e;
        }
        __syncthreads();
    }

    float inv = 1.f / denom;
    float* Xb = g_X + (b*LQ + ib*16 + i2) * DM + h*DK;
    *(float4*)&Xb[g*4] = make_float4(acc.x*inv, acc.y*inv, acc.z*inv, acc.w*inv);
}

// ---------------------------------------------------------------------------
extern "C" void kernel_launch(void* const* d_in, const int* in_sizes, int n_in,
                              void* d_out, int out_size)
{
    const float* query = (const float*)d_in[0];
    const float* key_  = (const float*)d_in[1];
    const float* value = (const float*)d_in[2];
    const int*   mask  = (const int*)  d_in[3];
    const float* Wq    = (const float*)d_in[4];
    const float* Wk    = (const float*)d_in[5];
    const float* Wv    = (const float*)d_in[6];
    const float* Wo    = (const float*)d_in[7];
    const float* wa    = (const float*)d_in[8];
    float* out = (float*)d_out;

    proj_kernel<<<dim3(8, 16, 3), 256>>>(query, key_, value, Wq, Wk, Wv, mask);
    attn_kernel<<<256, 256>>>(wa);
    out_gemm<<<dim3(8, 8, 4), 256>>>(Wo, out);
    reduce_out<<<128, 256>>>(out);
}

// round 10
// speedup vs baseline: 1.2573x; 1.0937x over previous
#include <cuda_runtime.h>
#include <cuda_bf16.h>
#include <mma.h>

using namespace nvcuda;

#define B_  2
#define H_  8
#define LQ  256
#define LK  512
#define DM  512
#define DK  64

#define AS_STRIDE 48   // 96B rows: 32B-aligned for ldmatrix, 2-way conflict max
#define BS_STRIDE 80   // 160B rows: 32B-aligned

// Scratch (device globals — no allocations allowed)
__device__ float g_Q[B_*LQ*DM];
__device__ float g_K[B_*LK*DM];
__device__ float g_V[B_*LK*DM];
__device__ float g_X[B_*LQ*DM];
__device__ float g_P[3][DM*DM];   // split-K partials for out GEMM (z=1..3)
__device__ int   g_idx[B_*LK];
__device__ int   g_cnt[B_];
__device__ float g_mult[B_];

__device__ __forceinline__ float fast_tanh(float x) {
    float r; asm("tanh.approx.f32 %0, %1;" : "=f"(r) : "f"(x)); return r;
}

// ---------------------------------------------------------------------------
// Deterministic mask compaction, 256 threads per batch: pair-load + scan.
// ---------------------------------------------------------------------------
__device__ void compact_body(const int* __restrict__ mask, int b) {
    __shared__ int s[256];
    int t = threadIdx.x;
    int m0 = (mask[b*LK + 2*t]     != 0) ? 1 : 0;
    int m1 = (mask[b*LK + 2*t + 1] != 0) ? 1 : 0;
    int ps = m0 + m1;
    s[t] = ps;
    __syncthreads();
    for (int off = 1; off < 256; off <<= 1) {
        int v = (t >= off) ? s[t - off] : 0;
        __syncthreads();
        if (t >= off) s[t] += v;
        __syncthreads();
    }
    int incl  = s[t];
    int total = s[255];
    int r0 = incl - ps + m0;
    int r1 = incl;
    if (m0) g_idx[b*LK + r0 - 1] = 2*t;
    if (m1) g_idx[b*LK + r1 - 1] = 2*t + 1;
    if (total == 0) {            // all-masked: uniform softmax fallback
        g_idx[b*LK + 2*t]     = 2*t;
        g_idx[b*LK + 2*t + 1] = 2*t + 1;
    }
    if (t == 0) {
        g_cnt[b]  = (total == 0) ? LK : total;
        g_mult[b] = (total == 0) ? 0.f : 1.f;
    }
}

// ---------------------------------------------------------------------------
// bf16x3-split tensor-core GEMM body.
// C[m0.., n0..] = A[:, kbeg..] @ W[kbeg.., n0..] over nk*16 K.
// Each operand split x = hi + lo (both bf16); acc += hi*hi + hi*lo + lo*hi
// (lo*lo dropped: rel err ~3e-5). fp32 accumulators, fixed order.
// 64x64 tile, 8 warps, each warp owns two 16x16 output tiles.
// ---------------------------------------------------------------------------
__device__ __forceinline__ void gemm_body(const float* __restrict__ A,
                                          const float* __restrict__ Bw,
                                          float* __restrict__ C,
                                          int m0, int n0, int kbeg, int nk)
{
    __shared__ __align__(32) __nv_bfloat16 As_hi[64][AS_STRIDE];
    __shared__ __align__(32) __nv_bfloat16 As_lo[64][AS_STRIDE];
    __shared__ __align__(32) __nv_bfloat16 Bs_hi[16][BS_STRIDE];
    __shared__ __align__(32) __nv_bfloat16 Bs_lo[16][BS_STRIDE];

    int t = threadIdx.x;
    int warp = t >> 5;
    int arow = t >> 2,  akc = (t & 3) * 4;     // A tile: 64 rows x 16 k (1 float4/thr)
    int bkr  = t >> 4,  bnc = (t & 15) * 4;    // B tile: 16 k x 64 n (1 float4/thr)

    const float* Ap = A  + (m0 + arow) * DM + kbeg + akc;
    const float* Bp = Bw + (kbeg + bkr) * DM + n0 + bnc;

    int wr = warp >> 1;           // warp tile-row 0..3 (16 rows each)
    int wc = (warp & 1) * 32;     // warp col offset: two 16-wide tiles

    wmma::fragment<wmma::accumulator, 16,16,16, float> acc0, acc1;
    wmma::fill_fragment(acc0, 0.f);
    wmma::fill_fragment(acc1, 0.f);

    float4 pa = *(const float4*)Ap;
    float4 pb = *(const float4*)Bp;

    for (int kt = 0; kt < nk; kt++) {
        {   // split-convert current tiles into smem
            float va[4] = {pa.x, pa.y, pa.z, pa.w};
            #pragma unroll
            for (int u = 0; u < 4; u++) {
                __nv_bfloat16 h = __float2bfloat16(va[u]);
                As_hi[arow][akc+u] = h;
                As_lo[arow][akc+u] = __float2bfloat16(va[u] - __bfloat162float(h));
            }
            float vb[4] = {pb.x, pb.y, pb.z, pb.w};
            #pragma unroll
            for (int u = 0; u < 4; u++) {
                __nv_bfloat16 h = __float2bfloat16(vb[u]);
                Bs_hi[bkr][bnc+u] = h;
                Bs_lo[bkr][bnc+u] = __float2bfloat16(vb[u] - __bfloat162float(h));
            }
        }
        __syncthreads();
        if (kt + 1 < nk) {                       // prefetch next tiles
            pa = *(const float4*)(Ap + (kt + 1) * 16);
            pb = *(const float4*)(Bp + (kt + 1) * 16 * DM);
        }
        wmma::fragment<wmma::matrix_a, 16,16,16, __nv_bfloat16, wmma::row_major> a_hi, a_lo;
        wmma::fragment<wmma::matrix_b, 16,16,16, __nv_bfloat16, wmma::row_major> b_hi, b_lo;
        wmma::load_matrix_sync(a_hi, &As_hi[wr*16][0], AS_STRIDE);
        wmma::load_matrix_sync(a_lo, &As_lo[wr*16][0], AS_STRIDE);

        wmma::load_matrix_sync(b_hi, &Bs_hi[0][wc], BS_STRIDE);
        wmma::load_matrix_sync(b_lo, &Bs_lo[0][wc], BS_STRIDE);
        wmma::mma_sync(acc0, a_hi, b_hi, acc0);
        wmma::mma_sync(acc0, a_hi, b_lo, acc0);
        wmma::mma_sync(acc0, a_lo, b_hi, acc0);

        wmma::load_matrix_sync(b_hi, &Bs_hi[0][wc+16], BS_STRIDE);
        wmma::load_matrix_sync(b_lo, &Bs_lo[0][wc+16], BS_STRIDE);
        wmma::mma_sync(acc1, a_hi, b_hi, acc1);
        wmma::mma_sync(acc1, a_hi, b_lo, acc1);
        wmma::mma_sync(acc1, a_lo, b_hi, acc1);
        __syncthreads();
    }
    wmma::store_matrix_sync(&C[(m0 + wr*16) * DM + n0 + wc],      acc0, DM, wmma::mem_row_major);
    wmma::store_matrix_sync(&C[(m0 + wr*16) * DM + n0 + wc + 16], acc1, DM, wmma::mem_row_major);
}

// ---------------------------------------------------------------------------
// Fused Q/K/V projections + mask compaction. Grid (8,16,3).
// ---------------------------------------------------------------------------
__global__ void __launch_bounds__(256) proj_kernel(const float* __restrict__ query,
                                                   const float* __restrict__ key_,
                                                   const float* __restrict__ value,
                                                   const float* __restrict__ Wq,
                                                   const float* __restrict__ Wk,
                                                   const float* __restrict__ Wv,
                                                   const int* __restrict__ mask)
{
    int z = blockIdx.z;
    const float* A; const float* W; float* C; int mrows;
    if (z == 0)      { A = query; W = Wq; C = g_Q; mrows = B_*LQ; }
    else if (z == 1) { A = key_;  W = Wk; C = g_K; mrows = B_*LK; }
    else             { A = value; W = Wv; C = g_V; mrows = B_*LK; }
    int m0 = blockIdx.y * 64;
    if (m0 >= mrows) {
        if (z == 0 && blockIdx.y == 8 && blockIdx.x < 2)
            compact_body(mask, blockIdx.x);
        return;
    }
    gemm_body(A, W, C, m0, blockIdx.x * 64, 0, DM/16);
}

// ---------------------------------------------------------------------------
// out = X @ Wo, SPLIT-K=4: z=0 writes d_out, z=1..3 write g_P[z-1].
// ---------------------------------------------------------------------------
__global__ void __launch_bounds__(256) out_gemm(const float* __restrict__ Wo,
                                                float* __restrict__ out)
{
    int z = blockIdx.z;
    float* C = (z == 0) ? out : g_P[z-1];
    gemm_body(g_X, Wo, C, blockIdx.y * 64, blockIdx.x * 64, z * (DM/4), DM/64);
}

// Deterministic fixed-order reduction of the 3 partial buffers into out.
// Grid 256 (was 128): 1 float4 per thread, better latency hiding.
__global__ void __launch_bounds__(256) reduce_out(float* __restrict__ out)
{
    int k = blockIdx.x * 256 + threadIdx.x;   // float4 index
    float4* o4 = (float4*)out;
    float4 a  = o4[k];
    float4 p0 = ((const float4*)g_P[0])[k];
    float4 p1 = ((const float4*)g_P[1])[k];
    float4 p2 = ((const float4*)g_P[2])[k];
    a.x += p0.x + p1.x + p2.x;
    a.y += p0.y + p1.y + p2.y;
    a.z += p0.z + p1.z + p2.z;
    a.w += p0.w + p1.w + p2.w;
    o4[k] = a;
}

// ---------------------------------------------------------------------------
// Fused additive attention (unchanged from R9 passing version).
// ---------------------------------------------------------------------------
__global__ void __launch_bounds__(256, 2) attn_kernel(const float* __restrict__ wa)
{
    __shared__ __align__(16) float qs[16][68];
    __shared__ __align__(16) float ks[32][68];
    __shared__ __align__(16) float vs[32][68];
    __shared__ float es[16][33];
    __shared__ __align__(16) float was[64];

    int blk = blockIdx.x;
    int ib = blk & 15, h = (blk >> 4) & 7, b = blk >> 7;
    int t = threadIdx.x, lane = t & 31, w = t >> 5;

    if (t < 64) was[t] = wa[t];

    const float* Qb = g_Q + (b*LQ + ib*16) * DM + h*DK;
    {
        int row = t >> 4, c4 = (t & 15) * 4;
        *(float4*)&qs[row][c4] = *(const float4*)&Qb[row*DM + c4];
    }

    int cnt    = g_cnt[b];
    float mult = g_mult[b];
    int nchunk = (cnt + 31) >> 5;

    float4 acc = make_float4(0,0,0,0);
    float denom = 0.f;
    int i2 = t >> 4, g = t & 15;

    const float* Kbase = g_K + b*LK*DM + h*DK;
    const float* Vbase = g_V + b*LK*DM + h*DK;
    const int*   idxb  = g_idx + b*LK;

    float4 pk[2], pv[2];
    #pragma unroll
    for (int u = 0; u < 2; u++) {
        int r = t + u*256;
        int row = r >> 4, c4 = (r & 15) * 4;
        int src = (row < cnt) ? idxb[row] : 0;
        pk[u] = *(const float4*)&Kbase[src*DM + c4];
        pv[u] = *(const float4*)&Vbase[src*DM + c4];
    }

    for (int c = 0; c < nchunk; c++) {
        #pragma unroll
        for (int u = 0; u < 2; u++) {
            int r = t + u*256;
            int row = r >> 4, c4 = (r & 15) * 4;
            *(float4*)&ks[row][c4] = pk[u];
            *(float4*)&vs[row][c4] = pv[u];
        }
        __syncthreads();
        if (c + 1 < nchunk) {
            #pragma unroll
            for (int u = 0; u < 2; u++) {
                int r = t + u*256;
                int row = r >> 4, c4 = (r & 15) * 4;
                int jj = (c + 1)*32 + row;
                int src = (jj < cnt) ? idxb[jj] : 0;
                pk[u] = *(const float4*)&Kbase[src*DM + c4];
                pv[u] = *(const float4*)&Vbase[src*DM + c4];
            }
        }
        bool valid = (c*32 + lane) < cnt;
        #pragma unroll
        for (int ii = 0; ii < 2; ii++) {
            int i = w*2 + ii;
            float s0 = 0.f, s1 = 0.f, s2 = 0.f, s3 = 0.f;
            #pragma unroll
            for (int d4 = 0; d4 < 16; d4++) {
                float4 q4 = *(const float4*)&qs[i][d4*4];
                float4 k4 = *(const float4*)&ks[lane][d4*4];
                float4 w4 = *(const float4*)&was[d4*4];
                s0 += fast_tanh(q4.x + k4.x) * w4.x;
                s1 += fast_tanh(q4.y + k4.y) * w4.y;
                s2 += fast_tanh(q4.z + k4.z) * w4.z;
                s3 += fast_tanh(q4.w + k4.w) * w4.w;
            }
            float s = (s0 + s1) + (s2 + s3);
            es[i][lane] = valid ? __expf(s * mult) : 0.f;
        }
        __syncthreads();
        #pragma unroll
        for (int j = 0; j < 32; j++) {
            float e = es[i2][j];
            float4 v = *(const float4*)&vs[j][g*4];
            acc.x += e*v.x; acc.y += e*v.y; acc.z += e*v.z; acc.w += e*v.w;
            denom += e;
        }
        __syncthreads();
    }

    float inv = 1.f / denom;
    float* Xb = g_X + (b*LQ + ib*16 + i2) * DM + h*DK;
    *(float4*)&Xb[g*4] = make_float4(acc.x*inv, acc.y*inv, acc.z*inv, acc.w*inv);
}

// ---------------------------------------------------------------------------
extern "C" void kernel_launch(void* const* d_in, const int* in_sizes, int n_in,
                              void* d_out, int out_size)
{
    const float* query = (const float*)d_in[0];
    const float* key_  = (const float*)d_in[1];
    const float* value = (const float*)d_in[2];
    const int*   mask  = (const int*)  d_in[3];
    const float* Wq    = (const float*)d_in[4];
    const float* Wk    = (const float*)d_in[5];
    const float* Wv    = (const float*)d_in[6];
    const float* Wo    = (const float*)d_in[7];
    const float* wa    = (const float*)d_in[8];
    float* out = (float*)d_out;

    proj_kernel<<<dim3(8, 16, 3), 256>>>(query, key_, value, Wq, Wk, Wv, mask);
    attn_kernel<<<256, 256>>>(wa);
    out_gemm<<<dim3(8, 8, 4), 256>>>(Wo, out);
    reduce_out<<<256, 256>>>(out);
}

// round 12
// speedup vs baseline: 1.2703x; 1.0103x over previous
#include <cuda_runtime.h>
#include <cuda_bf16.h>
#include <mma.h>

using namespace nvcuda;

#define B_  2
#define H_  8
#define LQ  256
#define LK  512
#define DM  512
#define DK  64

#define AS_STRIDE 48
#define BS_STRIDE 80

// Scratch (device globals — no allocations allowed)
__device__ float g_Q[B_*LQ*DM];
__device__ float g_K[B_*LK*DM];
__device__ float g_V[B_*LK*DM];
__device__ float g_X[B_*LQ*DM];
__device__ float g_P[3][DM*DM];   // split-K partials for out GEMM (z=1..3)
__device__ int   g_idx[B_*LK];
__device__ int   g_cnt[B_];
__device__ float g_mult[B_];

__device__ __forceinline__ float fast_tanh(float x) {
    float r; asm("tanh.approx.f32 %0, %1;" : "=f"(r) : "f"(x)); return r;
}

// ---------------------------------------------------------------------------
// Deterministic mask compaction, 256 threads per batch: pair-load + scan.
// ---------------------------------------------------------------------------
__device__ void compact_body(const int* __restrict__ mask, int b) {
    __shared__ int s[256];
    int t = threadIdx.x;
    int m0 = (mask[b*LK + 2*t]     != 0) ? 1 : 0;
    int m1 = (mask[b*LK + 2*t + 1] != 0) ? 1 : 0;
    int ps = m0 + m1;
    s[t] = ps;
    __syncthreads();
    for (int off = 1; off < 256; off <<= 1) {
        int v = (t >= off) ? s[t - off] : 0;
        __syncthreads();
        if (t >= off) s[t] += v;
        __syncthreads();
    }
    int incl  = s[t];
    int total = s[255];
    int r0 = incl - ps + m0;
    int r1 = incl;
    if (m0) g_idx[b*LK + r0 - 1] = 2*t;
    if (m1) g_idx[b*LK + r1 - 1] = 2*t + 1;
    if (total == 0) {            // all-masked: uniform softmax fallback
        g_idx[b*LK + 2*t]     = 2*t;
        g_idx[b*LK + 2*t + 1] = 2*t + 1;
    }
    if (t == 0) {
        g_cnt[b]  = (total == 0) ? LK : total;
        g_mult[b] = (total == 0) ? 0.f : 1.f;
    }
}

// ---------------------------------------------------------------------------
// bf16x3-split tensor-core GEMM body (verified R10: rel_err 6.6e-6).
// ---------------------------------------------------------------------------
__device__ __forceinline__ void gemm_body(const float* __restrict__ A,
                                          const float* __restrict__ Bw,
                                          float* __restrict__ C,
                                          int m0, int n0, int kbeg, int nk)
{
    __shared__ __align__(32) __nv_bfloat16 As_hi[64][AS_STRIDE];
    __shared__ __align__(32) __nv_bfloat16 As_lo[64][AS_STRIDE];
    __shared__ __align__(32) __nv_bfloat16 Bs_hi[16][BS_STRIDE];
    __shared__ __align__(32) __nv_bfloat16 Bs_lo[16][BS_STRIDE];

    int t = threadIdx.x;
    int warp = t >> 5;
    int arow = t >> 2,  akc = (t & 3) * 4;
    int bkr  = t >> 4,  bnc = (t & 15) * 4;

    const float* Ap = A  + (m0 + arow) * DM + kbeg + akc;
    const float* Bp = Bw + (kbeg + bkr) * DM + n0 + bnc;

    int wr = warp >> 1;
    int wc = (warp & 1) * 32;

    wmma::fragment<wmma::accumulator, 16,16,16, float> acc0, acc1;
    wmma::fill_fragment(acc0, 0.f);
    wmma::fill_fragment(acc1, 0.f);

    float4 pa = *(const float4*)Ap;
    float4 pb = *(const float4*)Bp;

    for (int kt = 0; kt < nk; kt++) {
        {
            float va[4] = {pa.x, pa.y, pa.z, pa.w};
            #pragma unroll
            for (int u = 0; u < 4; u++) {
                __nv_bfloat16 h = __float2bfloat16(va[u]);
                As_hi[arow][akc+u] = h;
                As_lo[arow][akc+u] = __float2bfloat16(va[u] - __bfloat162float(h));
            }
            float vb[4] = {pb.x, pb.y, pb.z, pb.w};
            #pragma unroll
            for (int u = 0; u < 4; u++) {
                __nv_bfloat16 h = __float2bfloat16(vb[u]);
                Bs_hi[bkr][bnc+u] = h;
                Bs_lo[bkr][bnc+u] = __float2bfloat16(vb[u] - __bfloat162float(h));
            }
        }
        __syncthreads();
        if (kt + 1 < nk) {
            pa = *(const float4*)(Ap + (kt + 1) * 16);
            pb = *(const float4*)(Bp + (kt + 1) * 16 * DM);
        }
        wmma::fragment<wmma::matrix_a, 16,16,16, __nv_bfloat16, wmma::row_major> a_hi, a_lo;
        wmma::fragment<wmma::matrix_b, 16,16,16, __nv_bfloat16, wmma::row_major> b_hi, b_lo;
        wmma::load_matrix_sync(a_hi, &As_hi[wr*16][0], AS_STRIDE);
        wmma::load_matrix_sync(a_lo, &As_lo[wr*16][0], AS_STRIDE);

        wmma::load_matrix_sync(b_hi, &Bs_hi[0][wc], BS_STRIDE);
        wmma::load_matrix_sync(b_lo, &Bs_lo[0][wc], BS_STRIDE);
        wmma::mma_sync(acc0, a_hi, b_hi, acc0);
        wmma::mma_sync(acc0, a_hi, b_lo, acc0);
        wmma::mma_sync(acc0, a_lo, b_hi, acc0);

        wmma::load_matrix_sync(b_hi, &Bs_hi[0][wc+16], BS_STRIDE);
        wmma::load_matrix_sync(b_lo, &Bs_lo[0][wc+16], BS_STRIDE);
        wmma::mma_sync(acc1, a_hi, b_hi, acc1);
        wmma::mma_sync(acc1, a_hi, b_lo, acc1);
        wmma::mma_sync(acc1, a_lo, b_hi, acc1);
        __syncthreads();
    }
    wmma::store_matrix_sync(&C[(m0 + wr*16) * DM + n0 + wc],      acc0, DM, wmma::mem_row_major);
    wmma::store_matrix_sync(&C[(m0 + wr*16) * DM + n0 + wc + 16], acc1, DM, wmma::mem_row_major);
}

// ---------------------------------------------------------------------------
__global__ void __launch_bounds__(256) proj_kernel(const float* __restrict__ query,
                                                   const float* __restrict__ key_,
                                                   const float* __restrict__ value,
                                                   const float* __restrict__ Wq,
                                                   const float* __restrict__ Wk,
                                                   const float* __restrict__ Wv,
                                                   const int* __restrict__ mask)
{
    int z = blockIdx.z;
    const float* A; const float* W; float* C; int mrows;
    if (z == 0)      { A = query; W = Wq; C = g_Q; mrows = B_*LQ; }
    else if (z == 1) { A = key_;  W = Wk; C = g_K; mrows = B_*LK; }
    else             { A = value; W = Wv; C = g_V; mrows = B_*LK; }
    int m0 = blockIdx.y * 64;
    if (m0 >= mrows) {
        if (z == 0 && blockIdx.y == 8 && blockIdx.x < 2)
            compact_body(mask, blockIdx.x);
        return;
    }
    gemm_body(A, W, C, m0, blockIdx.x * 64, 0, DM/16);
}

__global__ void __launch_bounds__(256) out_gemm(const float* __restrict__ Wo,
                                                float* __restrict__ out)
{
    int z = blockIdx.z;
    float* C = (z == 0) ? out : g_P[z-1];
    gemm_body(g_X, Wo, C, blockIdx.y * 64, blockIdx.x * 64, z * (DM/4), DM/64);
}

// Deterministic fixed-order reduction. Grid 64: 4 float4-quads per thread =
// 16 independent loads in flight (MLP=16 -> DRAM lat/16 per the LDG model).
__global__ void __launch_bounds__(256) reduce_out(float* __restrict__ out)
{
    int base = blockIdx.x * 256 + threadIdx.x;   // float4 index
    float4* o4 = (float4*)out;
    float4 a[4], p0[4], p1[4], p2[4];
    #pragma unroll
    for (int u = 0; u < 4; u++) {
        int k = base + u * 16384;                // 64*256 = 16384 stride
        a[u]  = o4[k];
        p0[u] = ((const float4*)g_P[0])[k];
        p1[u] = ((const float4*)g_P[1])[k];
        p2[u] = ((const float4*)g_P[2])[k];
    }
    #pragma unroll
    for (int u = 0; u < 4; u++) {
        int k = base + u * 16384;
        a[u].x += p0[u].x + p1[u].x + p2[u].x;
        a[u].y += p0[u].y + p1[u].y + p2[u].y;
        a[u].z += p0[u].z + p1[u].z + p2[u].z;
        a[u].w += p0[u].w + p1[u].w + p2[u].w;
        o4[k] = a[u];
    }
}

// ---------------------------------------------------------------------------
// Fused additive attention, SOFTWARE-PIPELINED phases.
// Iteration c computes phase-1(c) (MUFU tanh scores -> es[c&1]) AND
// phase-2(c-1) (FMA e*v from es[(c-1)&1], vs[(c-1)&1]) between the SAME
// barrier pair, so the scheduler interleaves FFMA into MUFU stall slots.
// ---------------------------------------------------------------------------
__global__ void __launch_bounds__(256, 2) attn_kernel(const float* __restrict__ wa)
{
    __shared__ __align__(16) float qs[16][68];
    __shared__ __align__(16) float ks[32][68];
    __shared__ __align__(16) float vs[2][32][68];
    __shared__ float es[2][16][33];
    __shared__ __align__(16) float was[64];

    int blk = blockIdx.x;
    int ib = blk & 15, h = (blk >> 4) & 7, b = blk >> 7;
    int t = threadIdx.x, lane = t & 31, w = t >> 5;

    if (t < 64) was[t] = wa[t];

    const float* Qb = g_Q + (b*LQ + ib*16) * DM + h*DK;
    {
        int row = t >> 4, c4 = (t & 15) * 4;
        *(float4*)&qs[row][c4] = *(const float4*)&Qb[row*DM + c4];
    }

    int cnt    = g_cnt[b];
    float mult = g_mult[b];
    int nchunk = (cnt + 31) >> 5;

    float4 acc = make_float4(0,0,0,0);
    float denom = 0.f;
    int i2 = t >> 4, g = t & 15;

    const float* Kbase = g_K + b*LK*DM + h*DK;
    const float* Vbase = g_V + b*LK*DM + h*DK;
    const int*   idxb  = g_idx + b*LK;

    int ld_row = t >> 4, ld_c4 = (t & 15) * 4;   // each thread: rows r, r+16
    float4 pk[2], pv[2];
    #pragma unroll
    for (int u = 0; u < 2; u++) {                 // prefetch chunk 0
        int row = ld_row + u*16;
        int src = (row < cnt) ? idxb[row] : 0;
        pk[u] = *(const float4*)&Kbase[src*DM + ld_c4];
        pv[u] = *(const float4*)&Vbase[src*DM + ld_c4];
    }

    for (int c = 0; c < nchunk; c++) {
        int buf = c & 1;
        #pragma unroll
        for (int u = 0; u < 2; u++) {
            int row = ld_row + u*16;
            *(float4*)&ks[row][ld_c4]      = pk[u];
            *(float4*)&vs[buf][row][ld_c4] = pv[u];
        }
        __syncthreads();
        if (c + 1 < nchunk) {                     // prefetch next chunk
            #pragma unroll
            for (int u = 0; u < 2; u++) {
                int jj = (c + 1)*32 + ld_row + u*16;
                int src = (jj < cnt) ? idxb[jj] : 0;
                pk[u] = *(const float4*)&Kbase[src*DM + ld_c4];
                pv[u] = *(const float4*)&Vbase[src*DM + ld_c4];
            }
        }
        // Phase 1 (chunk c): warp w owns rows 2w, 2w+1; lane = local j.
        bool valid = (c*32 + lane) < cnt;
        #pragma unroll
        for (int ii = 0; ii < 2; ii++) {
            int i = w*2 + ii;
            float s0 = 0.f, s1 = 0.f, s2 = 0.f, s3 = 0.f;
            #pragma unroll
            for (int d4 = 0; d4 < 16; d4++) {
                float4 q4 = *(const float4*)&qs[i][d4*4];
                float4 k4 = *(const float4*)&ks[lane][d4*4];
                float4 w4 = *(const float4*)&was[d4*4];
                s0 += fast_tanh(q4.x + k4.x) * w4.x;
                s1 += fast_tanh(q4.y + k4.y) * w4.y;
                s2 += fast_tanh(q4.z + k4.z) * w4.z;
                s3 += fast_tanh(q4.w + k4.w) * w4.w;
            }
            float s = (s0 + s1) + (s2 + s3);
            es[buf][i][lane] = valid ? __expf(s * mult) : 0.f;
        }
        // Phase 2 (chunk c-1): independent of phase 1 -> interleaved issue.
        if (c > 0) {
            int pbuf = buf ^ 1;
            #pragma unroll
            for (int j = 0; j < 32; j++) {
                float e = es[pbuf][i2][j];
                float4 v = *(const float4*)&vs[pbuf][j][g*4];
                acc.x += e*v.x; acc.y += e*v.y; acc.z += e*v.z; acc.w += e*v.w;
                denom += e;
            }
        }
        __syncthreads();
    }
    // Epilogue: phase 2 for the last chunk.
    {
        int pbuf = (nchunk - 1) & 1;
        #pragma unroll
        for (int j = 0; j < 32; j++) {
            float e = es[pbuf][i2][j];
            float4 v = *(const float4*)&vs[pbuf][j][g*4];
            acc.x += e*v.x; acc.y += e*v.y; acc.z += e*v.z; acc.w += e*v.w;
            denom += e;
        }
    }

    float inv = 1.f / denom;
    float* Xb = g_X + (b*LQ + ib*16 + i2) * DM + h*DK;
    *(float4*)&Xb[g*4] = make_float4(acc.x*inv, acc.y*inv, acc.z*inv, acc.w*inv);
}

// ---------------------------------------------------------------------------
extern "C" void kernel_launch(void* const* d_in, const int* in_sizes, int n_in,
                              void* d_out, int out_size)
{
    const float* query = (const float*)d_in[0];
    const float* key_  = (const float*)d_in[1];
    const float* value = (const float*)d_in[2];
    const int*   mask  = (const int*)  d_in[3];
    const float* Wq    = (const float*)d_in[4];
    const float* Wk    = (const float*)d_in[5];
    const float* Wv    = (const float*)d_in[6];
    const float* Wo    = (const float*)d_in[7];
    const float* wa    = (const float*)d_in[8];
    float* out = (float*)d_out;

    proj_kernel<<<dim3(8, 16, 3), 256>>>(query, key_, value, Wq, Wk, Wv, mask);
    attn_kernel<<<256, 256>>>(wa);
    out_gemm<<<dim3(8, 8, 4), 256>>>(Wo, out);
    reduce_out<<<64, 256>>>(out);
}